// round 7
// baseline (speedup 1.0000x reference)
#include <cuda_runtime.h>
#include <cstdint>

// Dendrite: out[b,d] = sum_{v=1..255} lin_w[v-1] * prod_{s: bit(7-s) of v} p_s + lin_b,
//   p_s = sigmoid(k*(w*x-q)).
// Multilinear Horner (255 packed FMA per 2 outputs) in f32x2; ONE packed pair
// (2 batch rows) per thread to maximize warp supply for latency hiding.

static constexpr int B = 8192;
static constexpr int D = 32;
static constexpr int S = 8;

using u64 = unsigned long long;

__device__ __forceinline__ u64 fma2(u64 a, u64 b, u64 c) {
    u64 d;
    asm("fma.rn.f32x2 %0, %1, %2, %3;" : "=l"(d) : "l"(a), "l"(b), "l"(c));
    return d;
}
__device__ __forceinline__ u64 pack2(float lo, float hi) {
    u64 d;
    asm("mov.b64 %0, {%1, %2};" : "=l"(d) : "f"(lo), "f"(hi));
    return d;
}
__device__ __forceinline__ void unpack2(u64 v, float& lo, float& hi) {
    asm("mov.b64 {%0, %1}, %2;" : "=f"(lo), "=f"(hi) : "l"(v));
}
__device__ __forceinline__ float fast_sigmoid_prehalved(float arg_half) {
    // sigmoid(a) = 0.5*tanh(a/2)+0.5 ; caller supplies a/2.
    float t;
    asm("tanh.approx.f32 %0, %1;" : "=f"(t) : "f"(arg_half));
    return fmaf(0.5f, t, 0.5f);
}

__global__ __launch_bounds__(128, 7)
void dendrite_kernel(const float* __restrict__ x,      // [B, 1, S]
                     const float* __restrict__ k,      // [D, S]
                     const float* __restrict__ w,      // [D, S]
                     const float* __restrict__ q,      // [D, S]
                     const float* __restrict__ lin_w,  // [1, 255]
                     const float* __restrict__ lin_b,  // [1]
                     float* __restrict__ out)          // [B, 1, D] -> b*D + d
{
    __shared__ __align__(16) u64 sW2[256];   // (c[v], c[v]); c[0]=0
    __shared__ float sA[S][D];               // [s][d] = 0.5*k*w
    __shared__ float sC[S][D];               // [s][d] = -0.5*k*q

    const int tid = threadIdx.x;   // 128 threads
#pragma unroll
    for (int i = tid; i < 256; i += 128) {
        const float cv = (i == 0) ? 0.0f : lin_w[i - 1];
        sW2[i] = pack2(cv, cv);
        const int dd = i >> 3, ss = i & 7;   // i = d*8 + s matches flat [D,S]
        const float kh = 0.5f * k[i];
        sA[ss][dd] = kh * w[i];
        sC[ss][dd] = -kh * q[i];
    }
    __syncthreads();

    const int d = tid & 31;                  // lane = d
    const int warp = tid >> 5;               // 4 warps/block
    const int b0 = (blockIdx.x * 4 + warp) * 2;   // 2 rows per thread

    // x rows b0, b0+1 (uniform across warp -> broadcast LDG.128)
    const float4* xp = reinterpret_cast<const float4*>(x + b0 * S);
    const float4 xa0 = xp[0], xb0 = xp[1];
    const float4 xa1 = xp[2], xb1 = xp[3];
    const float xs0[8] = {xa0.x, xa0.y, xa0.z, xa0.w, xb0.x, xb0.y, xb0.z, xb0.w};
    const float xs1[8] = {xa1.x, xa1.y, xa1.z, xa1.w, xb1.x, xb1.y, xb1.z, xb1.w};

    // Packed sigmoids: P[s] = (p_s row0, p_s row1)
    u64 P[8];
#pragma unroll
    for (int s = 0; s < 8; ++s) {
        const float A = sA[s][d];
        const float C = sC[s][d];
        P[s] = pack2(fast_sigmoid_prehalved(fmaf(A, xs0[s], C)),
                     fast_sigmoid_prehalved(fmaf(A, xs1[s], C)));
    }

    // Horner inner tree over lo bits (bit0<->p7, bit1<->p6, bit2<->p5, bit3<->p4);
    // first outer level (p3) folded into the hi loop; u[0..7] partials live.
    u64 u[8];
    u64 stash;
    const ulonglong2* W2 = reinterpret_cast<const ulonglong2*>(sW2);
#pragma unroll
    for (int hi = 0; hi < 16; ++hi) {
        const ulonglong2 q0 = W2[hi * 8 + 0], q1 = W2[hi * 8 + 1];
        const ulonglong2 q2 = W2[hi * 8 + 2], q3 = W2[hi * 8 + 3];
        const ulonglong2 q4 = W2[hi * 8 + 4], q5 = W2[hi * 8 + 5];
        const ulonglong2 q6 = W2[hi * 8 + 6], q7 = W2[hi * 8 + 7];

        // level A (p7): 8 fma2
        const u64 e0 = fma2(P[7], q0.y, q0.x);
        const u64 e1 = fma2(P[7], q1.y, q1.x);
        const u64 e2 = fma2(P[7], q2.y, q2.x);
        const u64 e3 = fma2(P[7], q3.y, q3.x);
        const u64 e4 = fma2(P[7], q4.y, q4.x);
        const u64 e5 = fma2(P[7], q5.y, q5.x);
        const u64 e6 = fma2(P[7], q6.y, q6.x);
        const u64 e7 = fma2(P[7], q7.y, q7.x);
        // level B (p6): 4
        const u64 f0 = fma2(P[6], e1, e0);
        const u64 f1 = fma2(P[6], e3, e2);
        const u64 f2 = fma2(P[6], e5, e4);
        const u64 f3 = fma2(P[6], e7, e6);
        // level C (p5): 2
        const u64 g0 = fma2(P[5], f1, f0);
        const u64 g1 = fma2(P[5], f3, f2);
        // level D (p4): 1
        const u64 inner = fma2(P[4], g1, g0);

        if ((hi & 1) == 0) stash = inner;
        else               u[hi >> 1] = fma2(P[3], inner, stash);
    }

    // Remaining outer Horner levels (p2, p1, p0)
    const u64 v0 = fma2(P[2], u[1], u[0]);
    const u64 v1 = fma2(P[2], u[3], u[2]);
    const u64 v2 = fma2(P[2], u[5], u[4]);
    const u64 v3 = fma2(P[2], u[7], u[6]);
    const u64 m0 = fma2(P[1], v1, v0);
    const u64 m1 = fma2(P[1], v3, v2);
    const u64 res = fma2(P[0], m1, m0);

    float rlo, rhi;
    unpack2(res, rlo, rhi);
    const float bias = lin_b[0];
    out[b0 * D + d]       = rlo + bias;
    out[(b0 + 1) * D + d] = rhi + bias;
}

extern "C" void kernel_launch(void* const* d_in, const int* in_sizes, int n_in,
                              void* d_out, int out_size) {
    const float* x     = (const float*)d_in[0];
    const float* k     = (const float*)d_in[1];
    const float* w     = (const float*)d_in[2];
    const float* q     = (const float*)d_in[3];
    // d_in[4] = mask (unused: fixed binary-expansion generation rule)
    const float* lin_w = (const float*)d_in[5];
    const float* lin_b = (const float*)d_in[6];
    float* out = (float*)d_out;

    // 128 threads = 4 warps; each thread: 2 batch rows -> 8 rows/block -> 1024 blocks
    dendrite_kernel<<<B / 8, 128>>>(x, k, w, q, lin_w, lin_b, out);
}

// round 8
// speedup vs baseline: 1.2704x; 1.2704x over previous
#include <cuda_runtime.h>
#include <cstdint>

// Dendrite: out[b,d] = sum_{v=1..255} lin_w[v-1] * prod_{s: bit(7-s) of v} p_s + lin_b,
//   p_s = sigmoid(k*(w*x-q)).
// Multilinear Horner: exactly 255 FMA per output (optimal), scalar f32.
// T=4 batch rows per thread amortizes the coefficient stream (16 LDS.128/output)
// and provides 4 independent dependency chains per coefficient load.
// 64-thread blocks -> 1024 blocks -> balanced 6.92 blocks/SM.

static constexpr int B = 8192;
static constexpr int D = 32;
static constexpr int S = 8;
static constexpr int T = 4;   // batch rows per thread

__device__ __forceinline__ float fast_sigmoid_prehalved(float arg_half) {
    // sigmoid(a) = 0.5*tanh(a/2)+0.5 ; caller supplies a/2.
    float t;
    asm("tanh.approx.f32 %0, %1;" : "=f"(t) : "f"(arg_half));
    return fmaf(0.5f, t, 0.5f);
}

__global__ __launch_bounds__(64)
void dendrite_kernel(const float* __restrict__ x,      // [B, 1, S]
                     const float* __restrict__ k,      // [D, S]
                     const float* __restrict__ w,      // [D, S]
                     const float* __restrict__ q,      // [D, S]
                     const float* __restrict__ lin_w,  // [1, 255]
                     const float* __restrict__ lin_b,  // [1]
                     float* __restrict__ out)          // [B, 1, D] -> b*D + d
{
    __shared__ __align__(16) float sW[256];  // c[v]; c[0]=0
    __shared__ float sA[S][D];               // [s][d] = 0.5*k*w
    __shared__ float sC[S][D];               // [s][d] = -0.5*k*q

    const int tid = threadIdx.x;   // 64 threads
#pragma unroll
    for (int i = tid; i < 256; i += 64) {
        sW[i] = (i == 0) ? 0.0f : lin_w[i - 1];
        const int dd = i >> 3, ss = i & 7;   // i = d*8 + s matches flat [D,S]
        const float kh = 0.5f * k[i];
        sA[ss][dd] = kh * w[i];
        sC[ss][dd] = -kh * q[i];
    }
    __syncthreads();

    const int d = tid & 31;                  // lane = d
    const int warp = tid >> 5;               // 2 warps/block
    const int b0 = (blockIdx.x * 2 + warp) * T;

    // x rows b0..b0+3 (uniform across warp -> broadcast LDG.128)
    const float4* xp = reinterpret_cast<const float4*>(x + b0 * S);
    float xs[T][8];
#pragma unroll
    for (int r = 0; r < T; ++r) {
        const float4 a = xp[2 * r], bb = xp[2 * r + 1];
        xs[r][0] = a.x;  xs[r][1] = a.y;  xs[r][2] = a.z;  xs[r][3] = a.w;
        xs[r][4] = bb.x; xs[r][5] = bb.y; xs[r][6] = bb.z; xs[r][7] = bb.w;
    }

    // P[r][s] = sigmoid(k*(w*x-q))
    float P[T][8];
#pragma unroll
    for (int s = 0; s < 8; ++s) {
        const float A = sA[s][d];
        const float C = sC[s][d];
#pragma unroll
        for (int r = 0; r < T; ++r)
            P[r][s] = fast_sigmoid_prehalved(fmaf(A, xs[r][s], C));
    }

    // Inner Horner over lo bits (bit0<->p7, bit1<->p6, bit2<->p5, bit3<->p4):
    // 15 FMA per (hi, r). First outer level (p3) folded into the hi loop so
    // only u[r][0..7] partials stay live.
    float u[T][8];
    float stash[T];
    const float4* W4 = reinterpret_cast<const float4*>(sW);
#pragma unroll
    for (int hi = 0; hi < 16; ++hi) {
        const float4 w0 = W4[hi * 4 + 0];
        const float4 w1 = W4[hi * 4 + 1];
        const float4 w2 = W4[hi * 4 + 2];
        const float4 w3 = W4[hi * 4 + 3];
#pragma unroll
        for (int r = 0; r < T; ++r) {
            const float p7 = P[r][7], p6 = P[r][6], p5 = P[r][5], p4 = P[r][4];
            // level A (p7): 8 FMA
            const float e0 = fmaf(p7, w0.y, w0.x);
            const float e1 = fmaf(p7, w0.w, w0.z);
            const float e2 = fmaf(p7, w1.y, w1.x);
            const float e3 = fmaf(p7, w1.w, w1.z);
            const float e4 = fmaf(p7, w2.y, w2.x);
            const float e5 = fmaf(p7, w2.w, w2.z);
            const float e6 = fmaf(p7, w3.y, w3.x);
            const float e7 = fmaf(p7, w3.w, w3.z);
            // level B (p6): 4
            const float f0 = fmaf(p6, e1, e0);
            const float f1 = fmaf(p6, e3, e2);
            const float f2 = fmaf(p6, e5, e4);
            const float f3 = fmaf(p6, e7, e6);
            // level C (p5): 2
            const float g0 = fmaf(p5, f1, f0);
            const float g1 = fmaf(p5, f3, f2);
            // level D (p4): 1
            const float inner = fmaf(p4, g1, g0);

            if ((hi & 1) == 0) stash[r] = inner;
            else               u[r][hi >> 1] = fmaf(P[r][3], inner, stash[r]);
        }
    }

    // Remaining outer Horner levels (p2, p1, p0): 7 FMA per row
    const float bias = lin_b[0];
#pragma unroll
    for (int r = 0; r < T; ++r) {
        const float p2 = P[r][2], p1 = P[r][1], p0 = P[r][0];
        const float v0 = fmaf(p2, u[r][1], u[r][0]);
        const float v1 = fmaf(p2, u[r][3], u[r][2]);
        const float v2 = fmaf(p2, u[r][5], u[r][4]);
        const float v3 = fmaf(p2, u[r][7], u[r][6]);
        const float m0 = fmaf(p1, v1, v0);
        const float m1 = fmaf(p1, v3, v2);
        const float res = fmaf(p0, m1, m0);
        out[(b0 + r) * D + d] = res + bias;
    }
}

extern "C" void kernel_launch(void* const* d_in, const int* in_sizes, int n_in,
                              void* d_out, int out_size) {
    const float* x     = (const float*)d_in[0];
    const float* k     = (const float*)d_in[1];
    const float* w     = (const float*)d_in[2];
    const float* q     = (const float*)d_in[3];
    // d_in[4] = mask (unused: fixed binary-expansion generation rule)
    const float* lin_w = (const float*)d_in[5];
    const float* lin_b = (const float*)d_in[6];
    float* out = (float*)d_out;

    // 64 threads = 2 warps; each thread: 4 batch rows -> 8 rows/block -> 1024 blocks
    dendrite_kernel<<<B / 8, 64>>>(x, k, w, q, lin_w, lin_b, out);
}